// round 15
// baseline (speedup 1.0000x reference)
#include <cuda_runtime.h>
#include <cuda_bf16.h>
#include <cuda_fp16.h>
#include <math.h>
#include <cstdint>

// ---------------- problem constants ----------------
#define BB 4
#define CC 3
#define HH 32
#define WW 32
#define NIMG 32
#define PP (NIMG*HH*WW)      // 32768 dataset patches
#define QQ (BB*HH*WW)        // 4096 queries
#define KD 27                // raw feature dim
#define KCH 5                // 5 k16 chunks (80 split dims: qh27|qh27|ql26)

#define NQB 16               // q blocks of 256 rows
#define PSPLIT 18            // 16*18 = 288 blocks = one wave at occ 2
#define NPG (PP/8)           // 4096 patch groups of 8
#define NGR (PP/16)          // 2048 groups of 16 (P-MMA k unit)
#define SGRP 4               // groups per smem stage (8 pg)

// ---------------- device scratch (no allocation allowed) -------------------
__device__ uint4  g_kfrag4[NPG * 2 * 32];         // 4 MB  chunks 0..3 B-fragments
__device__ uint4  g_kfrag2[NPG * 16];             // 1 MB  chunk 4 B-fragments
__device__ uint4  g_qfrag[(QQ/16) * KCH * 32];    // 640KB A-fragments
__device__ uint2  g_vfrag[NGR * 32];              // 512KB P-MMA B-fragments (f16)
__device__ float  g_bias[PP];                     // per-patch logit bias (log2)
__device__ float  g_partial[QQ * PSPLIT * 8];     // m,sw,c0,c1,c2 per (q,split)

// ---------------- helpers ----------------------------------------------
__device__ __forceinline__ float ex2f(float x) {
    float r; asm("ex2.approx.f32 %0,%1;" : "=f"(r) : "f"(x)); return r;
}
__device__ __forceinline__ unsigned pack_f16x2(float lo, float hi) {
    unsigned r;
    asm("cvt.rn.f16x2.f32 %0, %1, %2;" : "=r"(r) : "f"(hi), "f"(lo));
    return r;
}
__device__ __forceinline__ unsigned ex2_f16x2(unsigned x) {
    unsigned r;
    asm("ex2.approx.f16x2 %0, %1;" : "=r"(r) : "r"(x));
    return r;
}
__device__ __forceinline__ uint32_t smem_u32(const void* p) {
    uint32_t a;
    asm("{ .reg .u64 t; cvta.to.shared.u64 t, %1; cvt.u32.u64 %0, t; }"
        : "=r"(a) : "l"(p));
    return a;
}
__device__ __forceinline__ void cp_async16(uint32_t dst, const void* src) {
    asm volatile("cp.async.cg.shared.global [%0], [%1], 16;"
                 :: "r"(dst), "l"(src));
}
#define CP_COMMIT() asm volatile("cp.async.commit_group;" ::: "memory")
#define CP_WAIT1()  asm volatile("cp.async.wait_group 1;" ::: "memory")

__device__ __forceinline__ void split_bf16(float v, unsigned short& h, unsigned short& l) {
    __nv_bfloat16 hb = __float2bfloat16_rn(v);
    float rem = v - __bfloat162float(hb);
    __nv_bfloat16 lb = __float2bfloat16_rn(rem);
    h = __bfloat16_as_ushort(hb);
    l = __bfloat16_as_ushort(lb);
}
// score MMA: bf16
#define MMA_BF16(d0,d1,d2,d3,a0,a1,a2,a3,b0,b1) \
    asm volatile("mma.sync.aligned.m16n8k16.row.col.f32.bf16.bf16.f32 " \
                 "{%0,%1,%2,%3}, {%4,%5,%6,%7}, {%8,%9}, {%0,%1,%2,%3};" \
                 : "+f"(d0), "+f"(d1), "+f"(d2), "+f"(d3) \
                 : "r"(a0), "r"(a1), "r"(a2), "r"(a3), "r"(b0), "r"(b1))
// P-MMA: f16 (weights & V in f16, f32 accumulate)
#define MMA_F16(d0,d1,d2,d3,a0,a1,a2,a3,b0,b1) \
    asm volatile("mma.sync.aligned.m16n8k16.row.col.f32.f16.f16.f32 " \
                 "{%0,%1,%2,%3}, {%4,%5,%6,%7}, {%8,%9}, {%0,%1,%2,%3};" \
                 : "+f"(d0), "+f"(d1), "+f"(d2), "+f"(d3) \
                 : "r"(a0), "r"(a1), "r"(a2), "r"(a3), "r"(b0), "r"(b1))

// ---------------------------------------------------------------------------
// Prep: score-MMA fragments (Q/K split-bf16, 80 dims), f16 V fragments, bias.
// A row: [qh(27) | qh(27) | ql(26)] ; B row: [kh(27) | kl(27) | kh(26)]
// ---------------------------------------------------------------------------
__global__ void prep_kernel(const float* __restrict__ x,
                            const float* __restrict__ images,
                            const float* __restrict__ mu_sched,
                            const float* __restrict__ sigma_sched,
                            const int* __restrict__ tptr)
{
    const int t = *tptr;
    const float mu = mu_sched[t];
    const float sg = sigma_sched[t];
    const float LOG2E = 1.4426950408889634f;
    const float inv2s2 = 1.0f / (2.0f * sg * sg);
    const float a  = 2.0f * mu * inv2s2 * LOG2E;
    const float nb = -mu * mu * inv2s2 * LOG2E;

    int gid = blockIdx.x * blockDim.x + threadIdx.x;

    if (gid < PP) {
        // ---- dataset patch: K fragments + bias ----
        float f[KD];
        unsigned short hb[KD], lb[KD];
        unsigned short v[80];
        int p = gid;
        int n = p >> 10, i = (p >> 5) & 31, j = p & 31;
        float pn = 0.0f;
        #pragma unroll
        for (int c = 0; c < CC; c++)
            #pragma unroll
            for (int di = 0; di < 3; di++)
                #pragma unroll
                for (int dj = 0; dj < 3; dj++) {
                    int ii = i + di - 1, jj = j + dj - 1;
                    float vv = 0.0f;
                    if (ii >= 0 && ii < HH && jj >= 0 && jj < WW)
                        vv = images[(((n*CC + c) << 5) + ii) * WW + jj];
                    f[c*9 + di*3 + dj] = vv;
                    pn += vv * vv;
                }
        #pragma unroll
        for (int k = 0; k < KD; k++) split_bf16(f[k], hb[k], lb[k]);
        #pragma unroll
        for (int k = 0; k < 80; k++)
            v[k] = (k < 27) ? hb[k] : (k < 54) ? lb[k-27] : hb[k-54];

        int pg = p >> 3, nn = p & 7;
        #pragma unroll
        for (int cp = 0; cp < 2; cp++) {
            int c0 = 32*cp, c1 = 32*cp + 16;
            #pragma unroll
            for (int tt = 0; tt < 4; tt++) {
                uint4 val;
                val.x = (unsigned)v[c0 + 2*tt]     | ((unsigned)v[c0 + 2*tt + 1] << 16);
                val.y = (unsigned)v[c0 + 2*tt + 8] | ((unsigned)v[c0 + 2*tt + 9] << 16);
                val.z = (unsigned)v[c1 + 2*tt]     | ((unsigned)v[c1 + 2*tt + 1] << 16);
                val.w = (unsigned)v[c1 + 2*tt + 8] | ((unsigned)v[c1 + 2*tt + 9] << 16);
                g_kfrag4[((pg*2 + cp) << 5) + nn*4 + tt] = val;
            }
        }
        unsigned* k2 = (unsigned*)g_kfrag2;
        #pragma unroll
        for (int tt = 0; tt < 4; tt++) {
            unsigned b0 = (unsigned)v[64 + 2*tt]     | ((unsigned)v[64 + 2*tt + 1] << 16);
            unsigned b1 = (unsigned)v[64 + 2*tt + 8] | ((unsigned)v[64 + 2*tt + 9] << 16);
            int lane = nn*4 + tt;
            k2[(pg << 6) + lane*2]     = b0;
            k2[(pg << 6) + lane*2 + 1] = b1;
        }
        g_bias[p] = nb * pn;
    } else if (gid < PP + QQ) {
        // ---- query: A fragments ----
        float f[KD];
        unsigned short hb[KD], lb[KD];
        unsigned short v[80];
        int q = gid - PP;
        int b = q >> 10, h = (q >> 5) & 31, w0 = q & 31;
        #pragma unroll
        for (int c = 0; c < CC; c++)
            #pragma unroll
            for (int di = 0; di < 3; di++)
                #pragma unroll
                for (int dj = 0; dj < 3; dj++) {
                    int ii = (h + di - 1) & 31, jj = (w0 + dj - 1) & 31;
                    f[c*9 + di*3 + dj] = a * x[(((b*CC + c) << 5) + ii) * WW + jj];
                }
        #pragma unroll
        for (int k = 0; k < KD; k++) split_bf16(f[k], hb[k], lb[k]);
        #pragma unroll
        for (int k = 0; k < 80; k++)
            v[k] = (k < 27) ? hb[k] : (k < 54) ? hb[k-27] : lb[k-54];

        int tile = q >> 4, r = q & 15, rg = r & 7, rh = r >> 3;
        unsigned* qf = (unsigned*)g_qfrag;
        #pragma unroll
        for (int c = 0; c < KCH; c++) {
            #pragma unroll
            for (int tt = 0; tt < 4; tt++) {
                unsigned lo = (unsigned)v[c*16 + 2*tt]     | ((unsigned)v[c*16 + 2*tt + 1] << 16);
                unsigned hi = (unsigned)v[c*16 + 2*tt + 8] | ((unsigned)v[c*16 + 2*tt + 9] << 16);
                unsigned base4 = (((tile*KCH + c) << 5) + rg*4 + tt) << 2;
                qf[base4 + rh]     = lo;
                qf[base4 + 2 + rh] = hi;
            }
        }
    } else if (gid < PP + QQ + NGR*32) {
        // ---- V fragments (f16) for P-MMA: cols = c0h,c1h,c2h,1, c0l,c1l,c2l,0
        int idx  = gid - (PP + QQ);
        int gr   = idx >> 5;
        int lane = idx & 31;
        int g    = lane >> 2;
        int t4   = lane & 3;
        float vals[4];
        #pragma unroll
        for (int e = 0; e < 4; e++) {
            int k = (e < 2) ? (2*t4 + e) : (2*t4 + 8 + (e - 2));
            int p = gr*16 + k;
            float val;
            if (g == 3) val = 1.0f;
            else if (g == 7) val = 0.0f;
            else {
                int c = (g < 3) ? g : (g - 4);
                int n = p >> 10, i = (p >> 5) & 31, j = p & 31;
                float pix = images[((n*CC + c) << 10) + (i << 5) + j];
                __half hh = __float2half_rn(pix);
                val = (g < 3) ? __half2float(hh)
                              : (pix - __half2float(hh));
            }
            vals[e] = val;
        }
        uint2 out;
        out.x = pack_f16x2(vals[0], vals[1]);
        out.y = pack_f16x2(vals[2], vals[3]);
        g_vfrag[(gr << 5) + lane] = out;
    }
}

// ---------------------------------------------------------------------------
// Main: bf16 score MMA + f16x2-exp + f16 P-MMA, epilogue pipelined 1 group back.
// ---------------------------------------------------------------------------
struct Stage {
    uint4 k4[8*64];     // 8192 B : 8 pg, chunks 0..3
    uint2 k2[8*32];     // 2048 B : 8 pg, chunk 4
    uint2 v[SGRP*32];   // 1024 B : P-MMA V-fragments (f16)
    float bias[64];     //  256 B
};

__global__ void __launch_bounds__(256, 2)
score_main_kernel()
{
    __shared__ __align__(16) Stage stg[2];

    const int bid  = blockIdx.x;
    const int qb   = bid & 15;
    const int sp   = bid >> 4;          // 0..17
    const int tid  = threadIdx.x;
    const int w    = tid >> 5;
    const int lane = tid & 31;
    const int t4   = lane & 3;
    const int g    = lane >> 2;

    uint4 af[2][KCH];
    #pragma unroll
    for (int rs = 0; rs < 2; rs++) {
        int tile = qb*16 + w*2 + rs;
        #pragma unroll
        for (int c = 0; c < KCH; c++)
            af[rs][c] = g_qfrag[((tile*KCH + c) << 5) + lane];
    }

    float m_[2][2];
    float o_[2][4];
    #pragma unroll
    for (int rs = 0; rs < 2; rs++) {
        m_[rs][0] = -1e30f; m_[rs][1] = -1e30f;
        o_[rs][0] = 0.f; o_[rs][1] = 0.f; o_[rs][2] = 0.f; o_[rs][3] = 0.f;
    }

    // pipelined previous-group state (registers only)
    float pE[2][4], pO[2][4];
    uint2 pvf;
    bool  have = false;

    const int Gg0 = (NGR * sp) / PSPLIT;
    const int Gg1 = (NGR * (sp + 1)) / PSPLIT;
    const int nstages = (Gg1 - Gg0 + SGRP - 1) / SGRP;

    uint32_t k4a[2], k2a[2], va[2], ba[2];
    #pragma unroll
    for (int s = 0; s < 2; s++) {
        k4a[s] = smem_u32(&stg[s].k4[0]);
        k2a[s] = smem_u32(&stg[s].k2[0]);
        va[s]  = smem_u32(&stg[s].v[0]);
        ba[s]  = smem_u32(&stg[s].bias[0]);
    }

    auto prefetch = [&](int st, int dst) {
        int gr0 = Gg0 + st * SGRP;
        if (gr0 >= Gg1) return;
        int cnt = (Gg1 - gr0 < SGRP) ? (Gg1 - gr0) : SGRP;
        const uint4* ks = g_kfrag4 + (size_t)(2*gr0) * 64;
        for (int i = tid; i < cnt*128; i += 256)
            cp_async16(k4a[dst] + i*16, ks + i);
        const uint4* k2s = g_kfrag2 + (size_t)(2*gr0) * 16;
        for (int i = tid; i < cnt*32; i += 256)
            cp_async16(k2a[dst] + i*16, k2s + i);
        const uint4* vs = (const uint4*)(g_vfrag + (gr0 << 5));
        for (int i = tid; i < cnt*16; i += 256)
            cp_async16(va[dst] + i*16, vs + i);
        const uint4* bs = (const uint4*)(g_bias + gr0*16);
        for (int i = tid; i < cnt*4; i += 256)
            cp_async16(ba[dst] + i*16, bs + i);
    };

    // epilogue of the PREVIOUS group (register-only)
    auto epilogue = [&]() {
        #pragma unroll
        for (int rs = 0; rs < 2; rs++) {
            float mx0 = fmaxf(fmaxf(pE[rs][0], pE[rs][1]), fmaxf(pO[rs][0], pO[rs][1]));
            mx0 = fmaxf(mx0, __shfl_xor_sync(0xffffffffu, mx0, 1, 4));
            mx0 = fmaxf(mx0, __shfl_xor_sync(0xffffffffu, mx0, 2, 4));
            float mn0 = fmaxf(m_[rs][0], mx0);
            float cr0 = ex2f(m_[rs][0] - mn0);
            o_[rs][0] *= cr0; o_[rs][1] *= cr0;
            m_[rs][0] = mn0;

            float mx1 = fmaxf(fmaxf(pE[rs][2], pE[rs][3]), fmaxf(pO[rs][2], pO[rs][3]));
            mx1 = fmaxf(mx1, __shfl_xor_sync(0xffffffffu, mx1, 1, 4));
            mx1 = fmaxf(mx1, __shfl_xor_sync(0xffffffffu, mx1, 2, 4));
            float mn1 = fmaxf(m_[rs][1], mx1);
            float cr1 = ex2f(m_[rs][1] - mn1);
            o_[rs][2] *= cr1; o_[rs][3] *= cr1;
            m_[rs][1] = mn1;

            unsigned a0 = ex2_f16x2(pack_f16x2(pE[rs][0] - mn0, pE[rs][1] - mn0));
            unsigned a1 = ex2_f16x2(pack_f16x2(pE[rs][2] - mn1, pE[rs][3] - mn1));
            unsigned a2 = ex2_f16x2(pack_f16x2(pO[rs][0] - mn0, pO[rs][1] - mn0));
            unsigned a3 = ex2_f16x2(pack_f16x2(pO[rs][2] - mn1, pO[rs][3] - mn1));
            MMA_F16(o_[rs][0], o_[rs][1], o_[rs][2], o_[rs][3],
                    a0, a1, a2, a3, pvf.x, pvf.y);
        }
    };

    prefetch(0, 0);
    CP_COMMIT();

    for (int st = 0; st < nstages; st++) {
        const int cur = st & 1;
        prefetch(st + 1, cur ^ 1);
        CP_COMMIT();
        CP_WAIT1();
        __syncthreads();

        const int gr0 = Gg0 + st * SGRP;
        const int cnt = (Gg1 - gr0 < SGRP) ? (Gg1 - gr0) : SGRP;
        const uint4*  kb4 = stg[cur].k4;
        const uint2*  kb2 = stg[cur].k2;
        const uint2*  vb  = stg[cur].v;
        const float*  bb  = stg[cur].bias;

        for (int gi = 0; gi < cnt; gi++) {
            uint4 e0 = kb4[(2*gi)*64      + lane];
            uint4 e1 = kb4[(2*gi)*64 + 32 + lane];
            uint2 e2 = kb2[(2*gi)*32      + lane];
            uint4 q0 = kb4[(2*gi+1)*64      + lane];
            uint4 q1 = kb4[(2*gi+1)*64 + 32 + lane];
            uint2 q2 = kb2[(2*gi+1)*32      + lane];
            float2 bE = *(const float2*)(bb + gi*16 + 2*t4);
            float2 bO = *(const float2*)(bb + gi*16 + 8 + 2*t4);
            uint2  vf = vb[gi*32 + lane];

            // ---------------- phase 1: 20 score MMAs (current group)
            float sE[2][4], sO[2][4];
            #pragma unroll
            for (int rs = 0; rs < 2; rs++) {
                sE[rs][0] = bE.x; sE[rs][1] = bE.y; sE[rs][2] = bE.x; sE[rs][3] = bE.y;
                sO[rs][0] = bO.x; sO[rs][1] = bO.y; sO[rs][2] = bO.x; sO[rs][3] = bO.y;
            }
            #pragma unroll
            for (int c = 0; c < KCH; c++) {
                unsigned be0, be1, bo0, bo1;
                if      (c == 0) { be0 = e0.x; be1 = e0.y; bo0 = q0.x; bo1 = q0.y; }
                else if (c == 1) { be0 = e0.z; be1 = e0.w; bo0 = q0.z; bo1 = q0.w; }
                else if (c == 2) { be0 = e1.x; be1 = e1.y; bo0 = q1.x; bo1 = q1.y; }
                else if (c == 3) { be0 = e1.z; be1 = e1.w; bo0 = q1.z; bo1 = q1.w; }
                else             { be0 = e2.x; be1 = e2.y; bo0 = q2.x; bo1 = q2.y; }
                MMA_BF16(sE[0][0],sE[0][1],sE[0][2],sE[0][3],
                         af[0][c].x,af[0][c].y,af[0][c].z,af[0][c].w, be0,be1);
                MMA_BF16(sO[0][0],sO[0][1],sO[0][2],sO[0][3],
                         af[0][c].x,af[0][c].y,af[0][c].z,af[0][c].w, bo0,bo1);
                MMA_BF16(sE[1][0],sE[1][1],sE[1][2],sE[1][3],
                         af[1][c].x,af[1][c].y,af[1][c].z,af[1][c].w, be0,be1);
                MMA_BF16(sO[1][0],sO[1][1],sO[1][2],sO[1][3],
                         af[1][c].x,af[1][c].y,af[1][c].z,af[1][c].w, bo0,bo1);
            }

            // ---------------- phase 2: epilogue of PREVIOUS group
            if (have) epilogue();

            // promote current -> previous
            #pragma unroll
            for (int rs = 0; rs < 2; rs++)
                #pragma unroll
                for (int i = 0; i < 4; i++) {
                    pE[rs][i] = sE[rs][i];
                    pO[rs][i] = sO[rs][i];
                }
            pvf = vf;
            have = true;
        }
        __syncthreads();
    }

    // drain final group
    epilogue();

    // epilogue: combine hi/lo columns and gather per-row state
    #pragma unroll
    for (int rs = 0; rs < 2; rs++) {
        float p0 = o_[rs][0] + __shfl_xor_sync(0xffffffffu, o_[rs][0], 2, 4);
        float p1 = o_[rs][1] + __shfl_xor_sync(0xffffffffu, o_[rs][1], 2, 4);
        float c2v = __shfl_sync(0xffffffffu, p0, 1, 4);
        float swv = __shfl_sync(0xffffffffu, p1, 1, 4);
        float r0 = o_[rs][2] + __shfl_xor_sync(0xffffffffu, o_[rs][2], 2, 4);
        float r1 = o_[rs][3] + __shfl_xor_sync(0xffffffffu, o_[rs][3], 2, 4);
        float c2v2 = __shfl_sync(0xffffffffu, r0, 1, 4);
        float swv2 = __shfl_sync(0xffffffffu, r1, 1, 4);

        if (t4 == 0) {
            int tile = qb*16 + w*2 + rs;
            int q0r = tile*16 + g;
            float* o = g_partial + ((size_t)q0r * PSPLIT + sp) * 8;
            o[0] = m_[rs][0]; o[1] = swv; o[2] = p0; o[3] = p1; o[4] = c2v;
            float* o2 = g_partial + ((size_t)(q0r + 8) * PSPLIT + sp) * 8;
            o2[0] = m_[rs][1]; o2[1] = swv2; o2[2] = r0; o2[3] = r1; o2[4] = c2v2;
        }
    }
}

// ---------------------------------------------------------------------------
// Finalize: merge PSPLIT partials per query (log2 domain), form output.
// ---------------------------------------------------------------------------
__global__ void finalize_kernel(const float* __restrict__ x,
                                const float* __restrict__ mu_sched,
                                const float* __restrict__ sigma_sched,
                                const int* __restrict__ tptr,
                                float* __restrict__ out)
{
    int q = blockIdx.x * blockDim.x + threadIdx.x;
    if (q >= QQ) return;

    const int t = *tptr;
    const float mu = mu_sched[t];
    const float sg = sigma_sched[t];
    const float is2 = 1.0f / (sg * sg);

    const float* pr = g_partial + (size_t)q * PSPLIT * 8;

    float M = -1e30f;
    #pragma unroll
    for (int i = 0; i < PSPLIT; i++) M = fmaxf(M, pr[i*8]);

    float S = 0.f, c0 = 0.f, c1 = 0.f, c2 = 0.f;
    #pragma unroll
    for (int i = 0; i < PSPLIT; i++) {
        float cr = ex2f(pr[i*8] - M);
        S  += pr[i*8 + 1] * cr;
        c0 += pr[i*8 + 2] * cr;
        c1 += pr[i*8 + 3] * cr;
        c2 += pr[i*8 + 4] * cr;
    }
    float inv = 1.0f / S;

    int b = q >> 10;
    int pix = q & 1023;

    out[((b*CC + 0) << 10) + pix] = -(x[((b*CC + 0) << 10) + pix] - mu * c0 * inv) * is2;
    out[((b*CC + 1) << 10) + pix] = -(x[((b*CC + 1) << 10) + pix] - mu * c1 * inv) * is2;
    out[((b*CC + 2) << 10) + pix] = -(x[((b*CC + 2) << 10) + pix] - mu * c2 * inv) * is2;
}

// ---------------------------------------------------------------------------
extern "C" void kernel_launch(void* const* d_in, const int* in_sizes, int n_in,
                              void* d_out, int out_size)
{
    const float* x      = (const float*)d_in[0];
    const float* images = (const float*)d_in[1];
    const float* mu_s   = (const float*)d_in[2];
    const float* sg_s   = (const float*)d_in[3];
    const int*   tptr   = (const int*)d_in[4];
    float* out = (float*)d_out;

    int nthreads = PP + QQ + NGR*32;
    prep_kernel<<<(nthreads + 255) / 256, 256>>>(x, images, mu_s, sg_s, tptr);
    score_main_kernel<<<NQB * PSPLIT, 256>>>();
    finalize_kernel<<<(QQ + 255) / 256, 256>>>(x, mu_s, sg_s, tptr, out);
}

// round 16
// speedup vs baseline: 1.2739x; 1.2739x over previous
#include <cuda_runtime.h>
#include <cuda_bf16.h>
#include <cuda_fp16.h>
#include <math.h>
#include <cstdint>

// ---------------- problem constants ----------------
#define BB 4
#define CC 3
#define HH 32
#define WW 32
#define NIMG 32
#define PP (NIMG*HH*WW)      // 32768 dataset patches
#define QQ (BB*HH*WW)        // 4096 queries
#define KD 27                // raw feature dim
#define KCH 3                // 3 k16 chunks: [q·kh (27) | q'·kl' (21)] = 48 dims

#define NQB 16               // q blocks of 256 rows
#define PSPLIT 18            // 16*18 = 288 blocks = one wave at occ 2
#define NPG (PP/8)           // 4096 patch groups of 8
#define NGR (PP/16)          // 2048 groups of 16 (P-MMA k unit)
#define SGRP 4               // groups per smem stage (8 pg)

// ---------------- device scratch (no allocation allowed) -------------------
__device__ uint2  g_kfrag[NPG * KCH * 32];        // 3 MB  score B-fragments (f16)
__device__ uint4  g_qfrag[(QQ/16) * KCH * 32];    // 384KB score A-fragments (f16)
__device__ uint2  g_vfrag[NGR * 32];              // 512KB P-MMA B-fragments (f16)
__device__ float  g_bias[PP];                     // per-patch logit bias (log2)
__device__ float  g_partial[QQ * PSPLIT * 8];     // m,sw,c0,c1,c2 per (q,split)

// ---------------- helpers ----------------------------------------------
__device__ __forceinline__ float ex2f(float x) {
    float r; asm("ex2.approx.f32 %0,%1;" : "=f"(r) : "f"(x)); return r;
}
__device__ __forceinline__ unsigned pack_f16x2(float lo, float hi) {
    unsigned r;
    asm("cvt.rn.f16x2.f32 %0, %1, %2;" : "=r"(r) : "f"(hi), "f"(lo));
    return r;
}
__device__ __forceinline__ unsigned ex2_f16x2(unsigned x) {
    unsigned r;
    asm("ex2.approx.f16x2 %0, %1;" : "=r"(r) : "r"(x));
    return r;
}
__device__ __forceinline__ uint32_t smem_u32(const void* p) {
    uint32_t a;
    asm("{ .reg .u64 t; cvta.to.shared.u64 t, %1; cvt.u32.u64 %0, t; }"
        : "=r"(a) : "l"(p));
    return a;
}
__device__ __forceinline__ void cp_async16(uint32_t dst, const void* src) {
    asm volatile("cp.async.cg.shared.global [%0], [%1], 16;"
                 :: "r"(dst), "l"(src));
}
#define CP_COMMIT() asm volatile("cp.async.commit_group;" ::: "memory")
#define CP_WAIT1()  asm volatile("cp.async.wait_group 1;" ::: "memory")

// f16 MMA (scores and P-MMA), f32 accumulate
#define MMA_F16(d0,d1,d2,d3,a0,a1,a2,a3,b0,b1) \
    asm volatile("mma.sync.aligned.m16n8k16.row.col.f32.f16.f16.f32 " \
                 "{%0,%1,%2,%3}, {%4,%5,%6,%7}, {%8,%9}, {%0,%1,%2,%3};" \
                 : "+f"(d0), "+f"(d1), "+f"(d2), "+f"(d3) \
                 : "r"(a0), "r"(a1), "r"(a2), "r"(a3), "r"(b0), "r"(b1))

// ---------------------------------------------------------------------------
// Prep: f16 score fragments + f16 V fragments + biases.
// K row (48): [ kh_f16(27) | f16(kl*2^11)(first 21 dims) | pad ]
// Q row (48): [ q_f16(27)  | f16(q*2^-11)(first 21 dims) | pad ]
// s = q.kh + (q*2^-11).(kl*2^11) = q.kh + q.kl   (delta_q.k dropped)
// ---------------------------------------------------------------------------
__global__ void prep_kernel(const float* __restrict__ x,
                            const float* __restrict__ images,
                            const float* __restrict__ mu_sched,
                            const float* __restrict__ sigma_sched,
                            const int* __restrict__ tptr)
{
    const int t = *tptr;
    const float mu = mu_sched[t];
    const float sg = sigma_sched[t];
    const float LOG2E = 1.4426950408889634f;
    const float inv2s2 = 1.0f / (2.0f * sg * sg);
    const float a  = 2.0f * mu * inv2s2 * LOG2E;
    const float nb = -mu * mu * inv2s2 * LOG2E;

    int gid = blockIdx.x * blockDim.x + threadIdx.x;

    if (gid < PP) {
        // ---- dataset patch: K fragments + bias ----
        float f[KD];
        unsigned short v[48];
        int p = gid;
        int n = p >> 10, i = (p >> 5) & 31, j = p & 31;
        float pn = 0.0f;
        #pragma unroll
        for (int c = 0; c < CC; c++)
            #pragma unroll
            for (int di = 0; di < 3; di++)
                #pragma unroll
                for (int dj = 0; dj < 3; dj++) {
                    int ii = i + di - 1, jj = j + dj - 1;
                    float vv = 0.0f;
                    if (ii >= 0 && ii < HH && jj >= 0 && jj < WW)
                        vv = images[(((n*CC + c) << 5) + ii) * WW + jj];
                    f[c*9 + di*3 + dj] = vv;
                    pn += vv * vv;
                }
        #pragma unroll
        for (int d = 0; d < KD; d++) {
            __half h = __float2half_rn(f[d]);
            v[d] = __half_as_ushort(h);
            if (d < 21) {
                float kl = (f[d] - __half2float(h)) * 2048.0f;   // kl * 2^11
                v[27 + d] = __half_as_ushort(__float2half_rn(kl));
            }
        }
        #pragma unroll
        for (int d = 21; d < 27; d++) /* dropped kl dims */ ;
        // (positions 48.. not stored; pad within chunks)
        unsigned short vv[48];
        #pragma unroll
        for (int d = 0; d < 48; d++) vv[d] = (d < 27 || (d >= 27 && d < 48)) ? v[d] : 0;
        // (v fully populated 0..47: 27 kh + 21 kl)

        int pg = p >> 3, nn = p & 7;
        #pragma unroll
        for (int cp = 0; cp < KCH; cp++) {
            int c0 = 16*cp;
            #pragma unroll
            for (int tt = 0; tt < 4; tt++) {
                uint2 val;
                val.x = (unsigned)vv[c0 + 2*tt]     | ((unsigned)vv[c0 + 2*tt + 1] << 16);
                val.y = (unsigned)vv[c0 + 2*tt + 8] | ((unsigned)vv[c0 + 2*tt + 9] << 16);
                g_kfrag[((pg*KCH + cp) << 5) + nn*4 + tt] = val;
            }
        }
        g_bias[p] = nb * pn;
    } else if (gid < PP + QQ) {
        // ---- query: A fragments ----
        float f[KD];
        unsigned short v[48];
        int q = gid - PP;
        int b = q >> 10, h = (q >> 5) & 31, w0 = q & 31;
        #pragma unroll
        for (int c = 0; c < CC; c++)
            #pragma unroll
            for (int di = 0; di < 3; di++)
                #pragma unroll
                for (int dj = 0; dj < 3; dj++) {
                    int ii = (h + di - 1) & 31, jj = (w0 + dj - 1) & 31;
                    f[c*9 + di*3 + dj] = a * x[(((b*CC + c) << 5) + ii) * WW + jj];
                }
        #pragma unroll
        for (int d = 0; d < KD; d++) {
            v[d] = __half_as_ushort(__float2half_rn(f[d]));
            if (d < 21)
                v[27 + d] = __half_as_ushort(__float2half_rn(f[d] * (1.0f/2048.0f)));
        }

        int tile = q >> 4, r = q & 15, rg = r & 7, rh = r >> 3;
        unsigned* qf = (unsigned*)g_qfrag;
        #pragma unroll
        for (int c = 0; c < KCH; c++) {
            #pragma unroll
            for (int tt = 0; tt < 4; tt++) {
                unsigned lo = (unsigned)v[c*16 + 2*tt]     | ((unsigned)v[c*16 + 2*tt + 1] << 16);
                unsigned hi = (unsigned)v[c*16 + 2*tt + 8] | ((unsigned)v[c*16 + 2*tt + 9] << 16);
                unsigned base4 = (((tile*KCH + c) << 5) + rg*4 + tt) << 2;
                qf[base4 + rh]     = lo;
                qf[base4 + 2 + rh] = hi;
            }
        }
    } else if (gid < PP + QQ + NGR*32) {
        // ---- V fragments (f16) for P-MMA: cols = c0h,c1h,c2h,1, c0l,c1l,c2l,0
        int idx  = gid - (PP + QQ);
        int gr   = idx >> 5;
        int lane = idx & 31;
        int g    = lane >> 2;
        int t4   = lane & 3;
        float vals[4];
        #pragma unroll
        for (int e = 0; e < 4; e++) {
            int k = (e < 2) ? (2*t4 + e) : (2*t4 + 8 + (e - 2));
            int p = gr*16 + k;
            float val;
            if (g == 3) val = 1.0f;
            else if (g == 7) val = 0.0f;
            else {
                int c = (g < 3) ? g : (g - 4);
                int n = p >> 10, i = (p >> 5) & 31, j = p & 31;
                float pix = images[((n*CC + c) << 10) + (i << 5) + j];
                __half hh = __float2half_rn(pix);
                val = (g < 3) ? __half2float(hh)
                              : (pix - __half2float(hh));
            }
            vals[e] = val;
        }
        uint2 out;
        out.x = pack_f16x2(vals[0], vals[1]);
        out.y = pack_f16x2(vals[2], vals[3]);
        g_vfrag[(gr << 5) + lane] = out;
    }
}

// ---------------------------------------------------------------------------
// Main: f16 score MMA (3 chunks) + f16x2-exp + f16 P-MMA flash-attention.
// ---------------------------------------------------------------------------
struct Stage {
    uint2 k[8*KCH*32];  // 6144 B : 8 pg x 3 chunks
    uint2 v[SGRP*32];   // 1024 B : P-MMA V-fragments (f16)
    float bias[64];     //  256 B
};

__global__ void __launch_bounds__(256, 2)
score_main_kernel()
{
    __shared__ __align__(16) Stage stg[2];

    const int bid  = blockIdx.x;
    const int qb   = bid & 15;
    const int sp   = bid >> 4;          // 0..17
    const int tid  = threadIdx.x;
    const int w    = tid >> 5;
    const int lane = tid & 31;
    const int t4   = lane & 3;
    const int g    = lane >> 2;

    uint4 af[2][KCH];
    #pragma unroll
    for (int rs = 0; rs < 2; rs++) {
        int tile = qb*16 + w*2 + rs;
        #pragma unroll
        for (int c = 0; c < KCH; c++)
            af[rs][c] = g_qfrag[((tile*KCH + c) << 5) + lane];
    }

    float m_[2][2];
    float o_[2][4];
    #pragma unroll
    for (int rs = 0; rs < 2; rs++) {
        m_[rs][0] = -1e30f; m_[rs][1] = -1e30f;
        o_[rs][0] = 0.f; o_[rs][1] = 0.f; o_[rs][2] = 0.f; o_[rs][3] = 0.f;
    }

    const int Gg0 = (NGR * sp) / PSPLIT;
    const int Gg1 = (NGR * (sp + 1)) / PSPLIT;
    const int nstages = (Gg1 - Gg0 + SGRP - 1) / SGRP;

    uint32_t ka[2], va[2], ba[2];
    #pragma unroll
    for (int s = 0; s < 2; s++) {
        ka[s] = smem_u32(&stg[s].k[0]);
        va[s] = smem_u32(&stg[s].v[0]);
        ba[s] = smem_u32(&stg[s].bias[0]);
    }

    auto prefetch = [&](int st, int dst) {
        int gr0 = Gg0 + st * SGRP;
        if (gr0 >= Gg1) return;
        int cnt = (Gg1 - gr0 < SGRP) ? (Gg1 - gr0) : SGRP;
        // K: per group = 2 pg * 3 chunks * 32 lanes * 8B = 1536 B = 96 uint4
        const uint4* ks = (const uint4*)(g_kfrag + (size_t)(2*gr0) * KCH * 32);
        for (int i = tid; i < cnt*96; i += 256)
            cp_async16(ka[dst] + i*16, ks + i);
        const uint4* vs = (const uint4*)(g_vfrag + (gr0 << 5));
        for (int i = tid; i < cnt*16; i += 256)
            cp_async16(va[dst] + i*16, vs + i);
        const uint4* bs = (const uint4*)(g_bias + gr0*16);
        for (int i = tid; i < cnt*4; i += 256)
            cp_async16(ba[dst] + i*16, bs + i);
    };

    prefetch(0, 0);
    CP_COMMIT();

    for (int st = 0; st < nstages; st++) {
        const int cur = st & 1;
        prefetch(st + 1, cur ^ 1);
        CP_COMMIT();
        CP_WAIT1();
        __syncthreads();

        const int gr0 = Gg0 + st * SGRP;
        const int cnt = (Gg1 - gr0 < SGRP) ? (Gg1 - gr0) : SGRP;
        const uint2*  kb = stg[cur].k;
        const uint2*  vb = stg[cur].v;
        const float*  bb = stg[cur].bias;

        for (int gi = 0; gi < cnt; gi++) {
            uint2 e0 = kb[((2*gi)*KCH + 0)*32 + lane];
            uint2 e1 = kb[((2*gi)*KCH + 1)*32 + lane];
            uint2 e2 = kb[((2*gi)*KCH + 2)*32 + lane];
            uint2 q0 = kb[((2*gi+1)*KCH + 0)*32 + lane];
            uint2 q1 = kb[((2*gi+1)*KCH + 1)*32 + lane];
            uint2 q2 = kb[((2*gi+1)*KCH + 2)*32 + lane];
            float2 bE = *(const float2*)(bb + gi*16 + 2*t4);
            float2 bO = *(const float2*)(bb + gi*16 + 8 + 2*t4);
            uint2  vf = vb[gi*32 + lane];

            // ---------------- phase 1: 12 score MMAs, 4 independent chains
            float sE[2][4], sO[2][4];
            #pragma unroll
            for (int rs = 0; rs < 2; rs++) {
                sE[rs][0] = bE.x; sE[rs][1] = bE.y; sE[rs][2] = bE.x; sE[rs][3] = bE.y;
                sO[rs][0] = bO.x; sO[rs][1] = bO.y; sO[rs][2] = bO.x; sO[rs][3] = bO.y;
            }
            #pragma unroll
            for (int c = 0; c < KCH; c++) {
                unsigned be0, be1, bo0, bo1;
                if      (c == 0) { be0 = e0.x; be1 = e0.y; bo0 = q0.x; bo1 = q0.y; }
                else if (c == 1) { be0 = e1.x; be1 = e1.y; bo0 = q1.x; bo1 = q1.y; }
                else             { be0 = e2.x; be1 = e2.y; bo0 = q2.x; bo1 = q2.y; }
                MMA_F16(sE[0][0],sE[0][1],sE[0][2],sE[0][3],
                        af[0][c].x,af[0][c].y,af[0][c].z,af[0][c].w, be0,be1);
                MMA_F16(sO[0][0],sO[0][1],sO[0][2],sO[0][3],
                        af[0][c].x,af[0][c].y,af[0][c].z,af[0][c].w, bo0,bo1);
                MMA_F16(sE[1][0],sE[1][1],sE[1][2],sE[1][3],
                        af[1][c].x,af[1][c].y,af[1][c].z,af[1][c].w, be0,be1);
                MMA_F16(sO[1][0],sO[1][1],sO[1][2],sO[1][3],
                        af[1][c].x,af[1][c].y,af[1][c].z,af[1][c].w, bo0,bo1);
            }

            // ---------------- phase 2: branchless softmax (f16x2 exp) + P-MMA
            #pragma unroll
            for (int rs = 0; rs < 2; rs++) {
                float mx0 = fmaxf(fmaxf(sE[rs][0], sE[rs][1]), fmaxf(sO[rs][0], sO[rs][1]));
                mx0 = fmaxf(mx0, __shfl_xor_sync(0xffffffffu, mx0, 1, 4));
                mx0 = fmaxf(mx0, __shfl_xor_sync(0xffffffffu, mx0, 2, 4));
                float mn0 = fmaxf(m_[rs][0], mx0);
                float cr0 = ex2f(m_[rs][0] - mn0);
                o_[rs][0] *= cr0; o_[rs][1] *= cr0;
                m_[rs][0] = mn0;

                float mx1 = fmaxf(fmaxf(sE[rs][2], sE[rs][3]), fmaxf(sO[rs][2], sO[rs][3]));
                mx1 = fmaxf(mx1, __shfl_xor_sync(0xffffffffu, mx1, 1, 4));
                mx1 = fmaxf(mx1, __shfl_xor_sync(0xffffffffu, mx1, 2, 4));
                float mn1 = fmaxf(m_[rs][1], mx1);
                float cr1 = ex2f(m_[rs][1] - mn1);
                o_[rs][2] *= cr1; o_[rs][3] *= cr1;
                m_[rs][1] = mn1;

                unsigned a0 = ex2_f16x2(pack_f16x2(sE[rs][0] - mn0, sE[rs][1] - mn0));
                unsigned a1 = ex2_f16x2(pack_f16x2(sE[rs][2] - mn1, sE[rs][3] - mn1));
                unsigned a2 = ex2_f16x2(pack_f16x2(sO[rs][0] - mn0, sO[rs][1] - mn0));
                unsigned a3 = ex2_f16x2(pack_f16x2(sO[rs][2] - mn1, sO[rs][3] - mn1));
                MMA_F16(o_[rs][0], o_[rs][1], o_[rs][2], o_[rs][3],
                        a0, a1, a2, a3, vf.x, vf.y);
            }
        }
        __syncthreads();
    }

    // epilogue: combine hi/lo columns and gather per-row state
    #pragma unroll
    for (int rs = 0; rs < 2; rs++) {
        float p0 = o_[rs][0] + __shfl_xor_sync(0xffffffffu, o_[rs][0], 2, 4);
        float p1 = o_[rs][1] + __shfl_xor_sync(0xffffffffu, o_[rs][1], 2, 4);
        float c2v = __shfl_sync(0xffffffffu, p0, 1, 4);
        float swv = __shfl_sync(0xffffffffu, p1, 1, 4);
        float r0 = o_[rs][2] + __shfl_xor_sync(0xffffffffu, o_[rs][2], 2, 4);
        float r1 = o_[rs][3] + __shfl_xor_sync(0xffffffffu, o_[rs][3], 2, 4);
        float c2v2 = __shfl_sync(0xffffffffu, r0, 1, 4);
        float swv2 = __shfl_sync(0xffffffffu, r1, 1, 4);

        if (t4 == 0) {
            int tile = qb*16 + w*2 + rs;
            int q0r = tile*16 + g;
            float* o = g_partial + ((size_t)q0r * PSPLIT + sp) * 8;
            o[0] = m_[rs][0]; o[1] = swv; o[2] = p0; o[3] = p1; o[4] = c2v;
            float* o2 = g_partial + ((size_t)(q0r + 8) * PSPLIT + sp) * 8;
            o2[0] = m_[rs][1]; o2[1] = swv2; o2[2] = r0; o2[3] = r1; o2[4] = c2v2;
        }
    }
}

// ---------------------------------------------------------------------------
// Finalize: merge PSPLIT partials per query (log2 domain), form output.
// ---------------------------------------------------------------------------
__global__ void finalize_kernel(const float* __restrict__ x,
                                const float* __restrict__ mu_sched,
                                const float* __restrict__ sigma_sched,
                                const int* __restrict__ tptr,
                                float* __restrict__ out)
{
    int q = blockIdx.x * blockDim.x + threadIdx.x;
    if (q >= QQ) return;

    const int t = *tptr;
    const float mu = mu_sched[t];
    const float sg = sigma_sched[t];
    const float is2 = 1.0f / (sg * sg);

    const float* pr = g_partial + (size_t)q * PSPLIT * 8;

    float M = -1e30f;
    #pragma unroll
    for (int i = 0; i < PSPLIT; i++) M = fmaxf(M, pr[i*8]);

    float S = 0.f, c0 = 0.f, c1 = 0.f, c2 = 0.f;
    #pragma unroll
    for (int i = 0; i < PSPLIT; i++) {
        float cr = ex2f(pr[i*8] - M);
        S  += pr[i*8 + 1] * cr;
        c0 += pr[i*8 + 2] * cr;
        c1 += pr[i*8 + 3] * cr;
        c2 += pr[i*8 + 4] * cr;
    }
    float inv = 1.0f / S;

    int b = q >> 10;
    int pix = q & 1023;

    out[((b*CC + 0) << 10) + pix] = -(x[((b*CC + 0) << 10) + pix] - mu * c0 * inv) * is2;
    out[((b*CC + 1) << 10) + pix] = -(x[((b*CC + 1) << 10) + pix] - mu * c1 * inv) * is2;
    out[((b*CC + 2) << 10) + pix] = -(x[((b*CC + 2) << 10) + pix] - mu * c2 * inv) * is2;
}

// ---------------------------------------------------------------------------
extern "C" void kernel_launch(void* const* d_in, const int* in_sizes, int n_in,
                              void* d_out, int out_size)
{
    const float* x      = (const float*)d_in[0];
    const float* images = (const float*)d_in[1];
    const float* mu_s   = (const float*)d_in[2];
    const float* sg_s   = (const float*)d_in[3];
    const int*   tptr   = (const int*)d_in[4];
    float* out = (float*)d_out;

    int nthreads = PP + QQ + NGR*32;
    prep_kernel<<<(nthreads + 255) / 256, 256>>>(x, images, mu_s, sg_s, tptr);
    score_main_kernel<<<NQB * PSPLIT, 256>>>();
    finalize_kernel<<<(QQ + 255) / 256, 256>>>(x, mu_s, sg_s, tptr, out);
}

// round 17
// speedup vs baseline: 1.4966x; 1.1748x over previous
#include <cuda_runtime.h>
#include <cuda_bf16.h>
#include <cuda_fp16.h>
#include <math.h>
#include <cstdint>

// ---------------- problem constants ----------------
#define BB 4
#define CC 3
#define HH 32
#define WW 32
#define NIMG 32
#define PP (NIMG*HH*WW)      // 32768 dataset patches
#define QQ (BB*HH*WW)        // 4096 queries
#define KD 27                // raw feature dim
#define KCH 2                // 2 k16 chunks: plain f16 q.k over 27 dims (5 pad)

#define NQB 16               // q blocks of 256 rows
#define PSPLIT 18            // 16*18 = 288 blocks = one wave at occ 2
#define NPG (PP/8)           // 4096 patch groups of 8
#define NGR (PP/16)          // 2048 groups of 16 (P-MMA k unit)
#define SGRP 4               // groups per smem stage (8 pg)

// ---------------- device scratch (no allocation allowed) -------------------
__device__ uint2  g_kfrag[NPG * KCH * 32];        // 2 MB  score B-fragments (f16)
__device__ uint4  g_qfrag[(QQ/16) * KCH * 32];    // 256KB score A-fragments (f16)
__device__ uint2  g_vfrag[NGR * 32];              // 512KB P-MMA B-fragments (f16)
__device__ float  g_bias[PP];                     // per-patch logit bias (log2)
__device__ float  g_partial[QQ * PSPLIT * 8];     // m,sw,c0,c1,c2 per (q,split)

// ---------------- helpers ----------------------------------------------
__device__ __forceinline__ float ex2f(float x) {
    float r; asm("ex2.approx.f32 %0,%1;" : "=f"(r) : "f"(x)); return r;
}
__device__ __forceinline__ unsigned pack_f16x2(float lo, float hi) {
    unsigned r;
    asm("cvt.rn.f16x2.f32 %0, %1, %2;" : "=r"(r) : "f"(hi), "f"(lo));
    return r;
}
__device__ __forceinline__ unsigned ex2_f16x2(unsigned x) {
    unsigned r;
    asm("ex2.approx.f16x2 %0, %1;" : "=r"(r) : "r"(x));
    return r;
}
__device__ __forceinline__ uint32_t smem_u32(const void* p) {
    uint32_t a;
    asm("{ .reg .u64 t; cvta.to.shared.u64 t, %1; cvt.u32.u64 %0, t; }"
        : "=r"(a) : "l"(p));
    return a;
}
__device__ __forceinline__ void cp_async16(uint32_t dst, const void* src) {
    asm volatile("cp.async.cg.shared.global [%0], [%1], 16;"
                 :: "r"(dst), "l"(src));
}
#define CP_COMMIT() asm volatile("cp.async.commit_group;" ::: "memory")
#define CP_WAIT1()  asm volatile("cp.async.wait_group 1;" ::: "memory")

// f16 MMA (scores and P-MMA), f32 accumulate
#define MMA_F16(d0,d1,d2,d3,a0,a1,a2,a3,b0,b1) \
    asm volatile("mma.sync.aligned.m16n8k16.row.col.f32.f16.f16.f32 " \
                 "{%0,%1,%2,%3}, {%4,%5,%6,%7}, {%8,%9}, {%0,%1,%2,%3};" \
                 : "+f"(d0), "+f"(d1), "+f"(d2), "+f"(d3) \
                 : "r"(a0), "r"(a1), "r"(a2), "r"(a3), "r"(b0), "r"(b1))

// ---------------------------------------------------------------------------
// Prep: f16 score fragments (27 dims, 5 pad) + f16 V fragments + biases.
// s = f16(q) . f16(k) + bias   (log2 domain)
// ---------------------------------------------------------------------------
__global__ void prep_kernel(const float* __restrict__ x,
                            const float* __restrict__ images,
                            const float* __restrict__ mu_sched,
                            const float* __restrict__ sigma_sched,
                            const int* __restrict__ tptr)
{
    const int t = *tptr;
    const float mu = mu_sched[t];
    const float sg = sigma_sched[t];
    const float LOG2E = 1.4426950408889634f;
    const float inv2s2 = 1.0f / (2.0f * sg * sg);
    const float a  = 2.0f * mu * inv2s2 * LOG2E;
    const float nb = -mu * mu * inv2s2 * LOG2E;

    int gid = blockIdx.x * blockDim.x + threadIdx.x;

    if (gid < PP) {
        // ---- dataset patch: K fragments + bias ----
        unsigned short v[32];
        int p = gid;
        int n = p >> 10, i = (p >> 5) & 31, j = p & 31;
        float pn = 0.0f;
        #pragma unroll
        for (int c = 0; c < CC; c++)
            #pragma unroll
            for (int di = 0; di < 3; di++)
                #pragma unroll
                for (int dj = 0; dj < 3; dj++) {
                    int ii = i + di - 1, jj = j + dj - 1;
                    float vv = 0.0f;
                    if (ii >= 0 && ii < HH && jj >= 0 && jj < WW)
                        vv = images[(((n*CC + c) << 5) + ii) * WW + jj];
                    pn += vv * vv;
                    v[c*9 + di*3 + dj] = __half_as_ushort(__float2half_rn(vv));
                }
        #pragma unroll
        for (int d = KD; d < 32; d++) v[d] = 0;

        int pg = p >> 3, nn = p & 7;
        #pragma unroll
        for (int cp = 0; cp < KCH; cp++) {
            int c0 = 16*cp;
            #pragma unroll
            for (int tt = 0; tt < 4; tt++) {
                uint2 val;
                val.x = (unsigned)v[c0 + 2*tt]     | ((unsigned)v[c0 + 2*tt + 1] << 16);
                val.y = (unsigned)v[c0 + 2*tt + 8] | ((unsigned)v[c0 + 2*tt + 9] << 16);
                g_kfrag[((pg*KCH + cp) << 5) + nn*4 + tt] = val;
            }
        }
        g_bias[p] = nb * pn;
    } else if (gid < PP + QQ) {
        // ---- query: A fragments ----
        unsigned short v[32];
        int q = gid - PP;
        int b = q >> 10, h = (q >> 5) & 31, w0 = q & 31;
        #pragma unroll
        for (int c = 0; c < CC; c++)
            #pragma unroll
            for (int di = 0; di < 3; di++)
                #pragma unroll
                for (int dj = 0; dj < 3; dj++) {
                    int ii = (h + di - 1) & 31, jj = (w0 + dj - 1) & 31;
                    float qv = a * x[(((b*CC + c) << 5) + ii) * WW + jj];
                    v[c*9 + di*3 + dj] = __half_as_ushort(__float2half_rn(qv));
                }
        #pragma unroll
        for (int d = KD; d < 32; d++) v[d] = 0;

        int tile = q >> 4, r = q & 15, rg = r & 7, rh = r >> 3;
        unsigned* qf = (unsigned*)g_qfrag;
        #pragma unroll
        for (int c = 0; c < KCH; c++) {
            #pragma unroll
            for (int tt = 0; tt < 4; tt++) {
                unsigned lo = (unsigned)v[c*16 + 2*tt]     | ((unsigned)v[c*16 + 2*tt + 1] << 16);
                unsigned hi = (unsigned)v[c*16 + 2*tt + 8] | ((unsigned)v[c*16 + 2*tt + 9] << 16);
                unsigned base4 = (((tile*KCH + c) << 5) + rg*4 + tt) << 2;
                qf[base4 + rh]     = lo;
                qf[base4 + 2 + rh] = hi;
            }
        }
    } else if (gid < PP + QQ + NGR*32) {
        // ---- V fragments (f16) for P-MMA: cols = c0h,c1h,c2h,1, c0l,c1l,c2l,0
        int idx  = gid - (PP + QQ);
        int gr   = idx >> 5;
        int lane = idx & 31;
        int g    = lane >> 2;
        int t4   = lane & 3;
        float vals[4];
        #pragma unroll
        for (int e = 0; e < 4; e++) {
            int k = (e < 2) ? (2*t4 + e) : (2*t4 + 8 + (e - 2));
            int p = gr*16 + k;
            float val;
            if (g == 3) val = 1.0f;
            else if (g == 7) val = 0.0f;
            else {
                int c = (g < 3) ? g : (g - 4);
                int n = p >> 10, i = (p >> 5) & 31, j = p & 31;
                float pix = images[((n*CC + c) << 10) + (i << 5) + j];
                __half hh = __float2half_rn(pix);
                val = (g < 3) ? __half2float(hh)
                              : (pix - __half2float(hh));
            }
            vals[e] = val;
        }
        uint2 out;
        out.x = pack_f16x2(vals[0], vals[1]);
        out.y = pack_f16x2(vals[2], vals[3]);
        g_vfrag[(gr << 5) + lane] = out;
    }
}

// ---------------------------------------------------------------------------
// Main: f16 score MMA (2 chunks) + f16x2-exp + f16 P-MMA flash-attention.
// ---------------------------------------------------------------------------
struct Stage {
    uint2 k[8*KCH*32];  // 4096 B : 8 pg x 2 chunks
    uint2 v[SGRP*32];   // 1024 B : P-MMA V-fragments (f16)
    float bias[64];     //  256 B
};

__global__ void __launch_bounds__(256, 2)
score_main_kernel()
{
    __shared__ __align__(16) Stage stg[2];

    const int bid  = blockIdx.x;
    const int qb   = bid & 15;
    const int sp   = bid >> 4;          // 0..17
    const int tid  = threadIdx.x;
    const int w    = tid >> 5;
    const int lane = tid & 31;
    const int t4   = lane & 3;
    const int g    = lane >> 2;

    uint4 af[2][KCH];
    #pragma unroll
    for (int rs = 0; rs < 2; rs++) {
        int tile = qb*16 + w*2 + rs;
        #pragma unroll
        for (int c = 0; c < KCH; c++)
            af[rs][c] = g_qfrag[((tile*KCH + c) << 5) + lane];
    }

    float m_[2][2];
    float o_[2][4];
    #pragma unroll
    for (int rs = 0; rs < 2; rs++) {
        m_[rs][0] = -1e30f; m_[rs][1] = -1e30f;
        o_[rs][0] = 0.f; o_[rs][1] = 0.f; o_[rs][2] = 0.f; o_[rs][3] = 0.f;
    }

    const int Gg0 = (NGR * sp) / PSPLIT;
    const int Gg1 = (NGR * (sp + 1)) / PSPLIT;
    const int nstages = (Gg1 - Gg0 + SGRP - 1) / SGRP;

    uint32_t ka[2], va[2], ba[2];
    #pragma unroll
    for (int s = 0; s < 2; s++) {
        ka[s] = smem_u32(&stg[s].k[0]);
        va[s] = smem_u32(&stg[s].v[0]);
        ba[s] = smem_u32(&stg[s].bias[0]);
    }

    auto prefetch = [&](int st, int dst) {
        int gr0 = Gg0 + st * SGRP;
        if (gr0 >= Gg1) return;
        int cnt = (Gg1 - gr0 < SGRP) ? (Gg1 - gr0) : SGRP;
        // K: per group = 2 pg * 2 chunks * 32 lanes * 8B = 1024 B = 64 uint4
        const uint4* ks = (const uint4*)(g_kfrag + (size_t)(2*gr0) * KCH * 32);
        for (int i = tid; i < cnt*64; i += 256)
            cp_async16(ka[dst] + i*16, ks + i);
        const uint4* vs = (const uint4*)(g_vfrag + (gr0 << 5));
        for (int i = tid; i < cnt*16; i += 256)
            cp_async16(va[dst] + i*16, vs + i);
        const uint4* bs = (const uint4*)(g_bias + gr0*16);
        for (int i = tid; i < cnt*4; i += 256)
            cp_async16(ba[dst] + i*16, bs + i);
    };

    prefetch(0, 0);
    CP_COMMIT();

    for (int st = 0; st < nstages; st++) {
        const int cur = st & 1;
        prefetch(st + 1, cur ^ 1);
        CP_COMMIT();
        CP_WAIT1();
        __syncthreads();

        const int gr0 = Gg0 + st * SGRP;
        const int cnt = (Gg1 - gr0 < SGRP) ? (Gg1 - gr0) : SGRP;
        const uint2*  kb = stg[cur].k;
        const uint2*  vb = stg[cur].v;
        const float*  bb = stg[cur].bias;

        for (int gi = 0; gi < cnt; gi++) {
            uint2 e0 = kb[((2*gi)*KCH + 0)*32 + lane];
            uint2 e1 = kb[((2*gi)*KCH + 1)*32 + lane];
            uint2 q0 = kb[((2*gi+1)*KCH + 0)*32 + lane];
            uint2 q1 = kb[((2*gi+1)*KCH + 1)*32 + lane];
            float2 bE = *(const float2*)(bb + gi*16 + 2*t4);
            float2 bO = *(const float2*)(bb + gi*16 + 8 + 2*t4);
            uint2  vf = vb[gi*32 + lane];

            // ---------------- phase 1: 8 score MMAs, 4 independent chains
            float sE[2][4], sO[2][4];
            #pragma unroll
            for (int rs = 0; rs < 2; rs++) {
                sE[rs][0] = bE.x; sE[rs][1] = bE.y; sE[rs][2] = bE.x; sE[rs][3] = bE.y;
                sO[rs][0] = bO.x; sO[rs][1] = bO.y; sO[rs][2] = bO.x; sO[rs][3] = bO.y;
            }
            #pragma unroll
            for (int c = 0; c < KCH; c++) {
                unsigned be0, be1, bo0, bo1;
                if (c == 0) { be0 = e0.x; be1 = e0.y; bo0 = q0.x; bo1 = q0.y; }
                else        { be0 = e1.x; be1 = e1.y; bo0 = q1.x; bo1 = q1.y; }
                MMA_F16(sE[0][0],sE[0][1],sE[0][2],sE[0][3],
                        af[0][c].x,af[0][c].y,af[0][c].z,af[0][c].w, be0,be1);
                MMA_F16(sO[0][0],sO[0][1],sO[0][2],sO[0][3],
                        af[0][c].x,af[0][c].y,af[0][c].z,af[0][c].w, bo0,bo1);
                MMA_F16(sE[1][0],sE[1][1],sE[1][2],sE[1][3],
                        af[1][c].x,af[1][c].y,af[1][c].z,af[1][c].w, be0,be1);
                MMA_F16(sO[1][0],sO[1][1],sO[1][2],sO[1][3],
                        af[1][c].x,af[1][c].y,af[1][c].z,af[1][c].w, bo0,bo1);
            }

            // ---------------- phase 2: branchless softmax (f16x2 exp) + P-MMA
            #pragma unroll
            for (int rs = 0; rs < 2; rs++) {
                float mx0 = fmaxf(fmaxf(sE[rs][0], sE[rs][1]), fmaxf(sO[rs][0], sO[rs][1]));
                mx0 = fmaxf(mx0, __shfl_xor_sync(0xffffffffu, mx0, 1, 4));
                mx0 = fmaxf(mx0, __shfl_xor_sync(0xffffffffu, mx0, 2, 4));
                float mn0 = fmaxf(m_[rs][0], mx0);
                float cr0 = ex2f(m_[rs][0] - mn0);
                o_[rs][0] *= cr0; o_[rs][1] *= cr0;
                m_[rs][0] = mn0;

                float mx1 = fmaxf(fmaxf(sE[rs][2], sE[rs][3]), fmaxf(sO[rs][2], sO[rs][3]));
                mx1 = fmaxf(mx1, __shfl_xor_sync(0xffffffffu, mx1, 1, 4));
                mx1 = fmaxf(mx1, __shfl_xor_sync(0xffffffffu, mx1, 2, 4));
                float mn1 = fmaxf(m_[rs][1], mx1);
                float cr1 = ex2f(m_[rs][1] - mn1);
                o_[rs][2] *= cr1; o_[rs][3] *= cr1;
                m_[rs][1] = mn1;

                unsigned a0 = ex2_f16x2(pack_f16x2(sE[rs][0] - mn0, sE[rs][1] - mn0));
                unsigned a1 = ex2_f16x2(pack_f16x2(sE[rs][2] - mn1, sE[rs][3] - mn1));
                unsigned a2 = ex2_f16x2(pack_f16x2(sO[rs][0] - mn0, sO[rs][1] - mn0));
                unsigned a3 = ex2_f16x2(pack_f16x2(sO[rs][2] - mn1, sO[rs][3] - mn1));
                MMA_F16(o_[rs][0], o_[rs][1], o_[rs][2], o_[rs][3],
                        a0, a1, a2, a3, vf.x, vf.y);
            }
        }
        __syncthreads();
    }

    // epilogue: combine hi/lo columns and gather per-row state
    #pragma unroll
    for (int rs = 0; rs < 2; rs++) {
        float p0 = o_[rs][0] + __shfl_xor_sync(0xffffffffu, o_[rs][0], 2, 4);
        float p1 = o_[rs][1] + __shfl_xor_sync(0xffffffffu, o_[rs][1], 2, 4);
        float c2v = __shfl_sync(0xffffffffu, p0, 1, 4);
        float swv = __shfl_sync(0xffffffffu, p1, 1, 4);
        float r0 = o_[rs][2] + __shfl_xor_sync(0xffffffffu, o_[rs][2], 2, 4);
        float r1 = o_[rs][3] + __shfl_xor_sync(0xffffffffu, o_[rs][3], 2, 4);
        float c2v2 = __shfl_sync(0xffffffffu, r0, 1, 4);
        float swv2 = __shfl_sync(0xffffffffu, r1, 1, 4);

        if (t4 == 0) {
            int tile = qb*16 + w*2 + rs;
            int q0r = tile*16 + g;
            float* o = g_partial + ((size_t)q0r * PSPLIT + sp) * 8;
            o[0] = m_[rs][0]; o[1] = swv; o[2] = p0; o[3] = p1; o[4] = c2v;
            float* o2 = g_partial + ((size_t)(q0r + 8) * PSPLIT + sp) * 8;
            o2[0] = m_[rs][1]; o2[1] = swv2; o2[2] = r0; o2[3] = r1; o2[4] = c2v2;
        }
    }
}

// ---------------------------------------------------------------------------
// Finalize: merge PSPLIT partials per query (log2 domain), form output.
// ---------------------------------------------------------------------------
__global__ void finalize_kernel(const float* __restrict__ x,
                                const float* __restrict__ mu_sched,
                                const float* __restrict__ sigma_sched,
                                const int* __restrict__ tptr,
                                float* __restrict__ out)
{
    int q = blockIdx.x * blockDim.x + threadIdx.x;
    if (q >= QQ) return;

    const int t = *tptr;
    const float mu = mu_sched[t];
    const float sg = sigma_sched[t];
    const float is2 = 1.0f / (sg * sg);

    const float* pr = g_partial + (size_t)q * PSPLIT * 8;

    float M = -1e30f;
    #pragma unroll
    for (int i = 0; i < PSPLIT; i++) M = fmaxf(M, pr[i*8]);

    float S = 0.f, c0 = 0.f, c1 = 0.f, c2 = 0.f;
    #pragma unroll
    for (int i = 0; i < PSPLIT; i++) {
        float cr = ex2f(pr[i*8] - M);
        S  += pr[i*8 + 1] * cr;
        c0 += pr[i*8 + 2] * cr;
        c1 += pr[i*8 + 3] * cr;
        c2 += pr[i*8 + 4] * cr;
    }
    float inv = 1.0f / S;

    int b = q >> 10;
    int pix = q & 1023;

    out[((b*CC + 0) << 10) + pix] = -(x[((b*CC + 0) << 10) + pix] - mu * c0 * inv) * is2;
    out[((b*CC + 1) << 10) + pix] = -(x[((b*CC + 1) << 10) + pix] - mu * c1 * inv) * is2;
    out[((b*CC + 2) << 10) + pix] = -(x[((b*CC + 2) << 10) + pix] - mu * c2 * inv) * is2;
}

// ---------------------------------------------------------------------------
extern "C" void kernel_launch(void* const* d_in, const int* in_sizes, int n_in,
                              void* d_out, int out_size)
{
    const float* x      = (const float*)d_in[0];
    const float* images = (const float*)d_in[1];
    const float* mu_s   = (const float*)d_in[2];
    const float* sg_s   = (const float*)d_in[3];
    const int*   tptr   = (const int*)d_in[4];
    float* out = (float*)d_out;

    int nthreads = PP + QQ + NGR*32;
    prep_kernel<<<(nthreads + 255) / 256, 256>>>(x, images, mu_s, sg_s, tptr);
    score_main_kernel<<<NQB * PSPLIT, 256>>>();
    finalize_kernel<<<(QQ + 255) / 256, 256>>>(x, mu_s, sg_s, tptr, out);
}